// round 1
// baseline (speedup 1.0000x reference)
#include <cuda_runtime.h>
#include <cstdint>
#include <cstdio>

#define Bm   8
#define Cm   1024
#define BCm  8192
#define Hm   56
#define Wm   56
#define HWm  3136
#define NB   256
#define NCH  5
#define CHUNK 1639       /* ceil(8192/5); last chunk = 1636 */
#define NCLS 30

// ---------------- device scratch (static: no allocations allowed) ----------
__device__ unsigned int g_scratch[(size_t)NCH * NB * HWm];  // ~16 MB, [chunk][bin][cell]
__device__ float        g_integ[(size_t)NB * HWm];          // 3.2 MB, [bin][cell], cell=(h-1)*56+(w-1)
__device__ int          g_reg[4];                           // xd, ys, yd
__device__ float        g_pooled[BCm];

// ---------------- K1: per-chunk per-cell histograms ------------------------
// Grid (28, NCH), block 128 (4 warps). Each warp handles one (row, w-half).
// Each LANE owns one spatial cell and a private 256-bin column in SMEM at
// hist[bin*32+lane] -> bank == lane -> conflict-free, atomic-free RMW.
__global__ void k_hist(const float* __restrict__ x) {
    extern __shared__ unsigned int sm[];
    const int tid  = threadIdx.x;
    const int warp = tid >> 5;
    const int lane = tid & 31;
    unsigned int* hist = sm + warp * (NB * 32);

    const int h = blockIdx.x * 2 + (warp >> 1);
    const int w = (warp & 1) * 32 + lane;
    const bool active = (w < Wm);

    // zero private column (thread-private, no sync needed anywhere)
    #pragma unroll 8
    for (int b = 0; b < NB; b++) hist[b * 32 + lane] = 0u;

    const int bc0 = blockIdx.y * CHUNK;
    const int bc1 = min(BCm, bc0 + CHUNK);

    if (active) {
        const float* p = x + (size_t)h * Wm + w;
        int bc = bc0;
        #define PROC(v) do {                                        \
            if ((v) >= 0.0f && (v) <= 1.0f) {                       \
                int bi = (int)((v) * 256.0f);                       \
                bi = min(bi, 255);                                  \
                hist[bi * 32 + lane] += 1u;                         \
            } } while (0)
        for (; bc + 8 <= bc1; bc += 8) {
            float v0 = p[(size_t)(bc + 0) * HWm];
            float v1 = p[(size_t)(bc + 1) * HWm];
            float v2 = p[(size_t)(bc + 2) * HWm];
            float v3 = p[(size_t)(bc + 3) * HWm];
            float v4 = p[(size_t)(bc + 4) * HWm];
            float v5 = p[(size_t)(bc + 5) * HWm];
            float v6 = p[(size_t)(bc + 6) * HWm];
            float v7 = p[(size_t)(bc + 7) * HWm];
            PROC(v0); PROC(v1); PROC(v2); PROC(v3);
            PROC(v4); PROC(v5); PROC(v6); PROC(v7);
        }
        for (; bc < bc1; bc++) {
            float v = p[(size_t)bc * HWm];
            PROC(v);
        }
        #undef PROC
        // store: scratch[chunk][bin][cell] — coalesced across lanes, CF LDS
        unsigned int* dst = g_scratch + (size_t)blockIdx.y * NB * HWm
                            + (size_t)h * Wm + w;
        #pragma unroll 4
        for (int b = 0; b < NB; b++)
            dst[(size_t)b * HWm] = hist[b * 32 + lane];
    }
}

// ---------------- K2: merge chunks + 2D prefix per bin ---------------------
// Grid 256 (one block per bin), block 256 threads.
__global__ void k_integ() {
    __shared__ float buf[Hm * 57];   // padded stride 57 -> conflict-free cumsums
    const int bin = blockIdx.x;
    const int tid = threadIdx.x;

    for (int cell = tid; cell < HWm; cell += 256) {
        unsigned int a = 0;
        #pragma unroll
        for (int ch = 0; ch < NCH; ch++)
            a += g_scratch[((size_t)ch * NB + bin) * HWm + cell];
        buf[(cell / Wm) * 57 + (cell % Wm)] = (float)a;
    }
    __syncthreads();
    if (tid < Hm) {                  // cumsum along w
        float r = 0.0f;
        for (int w = 0; w < Wm; w++) { r += buf[tid * 57 + w]; buf[tid * 57 + w] = r; }
    }
    __syncthreads();
    if (tid < Wm) {                  // cumsum along h
        float r = 0.0f;
        for (int h = 0; h < Hm; h++) { r += buf[h * 57 + tid]; buf[h * 57 + tid] = r; }
    }
    __syncthreads();
    for (int cell = tid; cell < HWm; cell += 256)
        g_integ[(size_t)bin * HWm + cell] = buf[(cell / Wm) * 57 + (cell % Wm)];
}

// ---------------- K3: EKLM (single block) ----------------------------------
__device__ __forceinline__ float wredsum(float v) {
    #pragma unroll
    for (int o = 16; o; o >>= 1) v += __shfl_xor_sync(0xffffffffu, v, o);
    return v;
}

// entropy of region [0:xd, ys:yd]; warp-collective (full warp), xs==0 so only
// 2 integral lookups per bin. Returns warp-uniform value.
__device__ float ent_region(int xd, int ys, int yd, int lane) {
    const int cA = (xd - 1) * Wm + (yd - 1);
    const int cB = (ys > 0) ? ((xd - 1) * Wm + (ys - 1)) : -1;
    float hv[8];
    float S = 0.0f;
    #pragma unroll
    for (int k = 0; k < 8; k++) {
        int b = k * 32 + lane;
        float a  = g_integ[(size_t)b * HWm + cA];
        float bb = (cB >= 0) ? g_integ[(size_t)b * HWm + cB] : 0.0f;
        hv[k] = a - bb;
        S += hv[k];
    }
    S = wredsum(S);
    float e = 0.0f;
    #pragma unroll
    for (int k = 0; k < 8; k++) {
        float pp = hv[k] / S;
        e -= pp * __log2f(pp + 1e-9f);
    }
    return wredsum(e);
}

__global__ void k_eklm() {
    extern __shared__ float sh[];            // NB*57 floats (row h=1 of integ)
    __shared__ float enty[Wm];
    __shared__ int   s_ys0;
    const int tid  = threadIdx.x;
    const int lane = tid & 31;
    const int warp = tid >> 5;

    // preload integ row (store-row 0) : sh[b*57 + w]
    for (int i = tid; i < NB * Wm; i += blockDim.x) {
        int b = i / Wm, w = i % Wm;
        sh[b * 57 + w] = g_integ[(size_t)b * HWm + w];
    }
    __syncthreads();

    // per-column entropies at h==0 (warp per column, 7 rounds)
    for (int w = warp; w < Wm; w += 8) {
        float hv[8];
        float S = 0.0f;
        #pragma unroll
        for (int k = 0; k < 8; k++) {
            int b = k * 32 + lane;
            float a  = sh[b * 57 + w];
            float bb = (w > 0) ? sh[b * 57 + w - 1] : 0.0f;
            hv[k] = a - bb;
            S += hv[k];
        }
        S = wredsum(S);
        float e = 0.0f;
        #pragma unroll
        for (int k = 0; k < 8; k++) {
            float pp = hv[k] / S;
            e -= pp * __log2f(pp + 1e-9f);
        }
        e = wredsum(e);
        if (lane == 0) enty[w] = e;
    }
    __syncthreads();

    if (tid == 0) {                          // argmax, first-occurrence
        float best = enty[0];
        int bi = 0;
        for (int w = 1; w < Wm; w++)
            if (enty[w] > best) { best = enty[w]; bi = w; }
        s_ys0 = bi;
    }
    __syncthreads();

    if (warp == 0) {
        const int ys0 = s_ys0;
        const float total = ent_region(Hm, 0, Wm, lane);
        int xd = 1, ys = ys0, yd = ys0 + 1;
        float Ts = ent_region(xd, ys, yd, lane) / total;
        bool done = false;
        int guard = 0;
        while (Ts < 0.9f && !done && guard < 256) {
            guard++;
            float ec = ent_region(xd, ys, yd, lane);
            bool c1 = (xd + 1 < Hm) && (ent_region(xd + 1, ys, yd, lane) > ec);
            bool c2 = !c1 && (ys - 1 >= 0) && (ent_region(xd, ys - 1, yd, lane) > ec);
            bool c3 = !c1 && !c2 && (yd + 1 < Wm) && (ent_region(xd, ys, yd + 1, lane) > ec);
            if (c1) xd++;
            else if (c2) ys--;
            else if (c3) yd++;
            done = !(c1 || c2 || c3);
            Ts = ent_region(xd, ys, yd, lane) / total;
        }
        if (lane == 0) { g_reg[0] = xd; g_reg[1] = ys; g_reg[2] = yd; }
    }
}

// ---------------- K4: region mean-pool -------------------------------------
__global__ void k_pool(const float* __restrict__ x) {
    const int bc = blockIdx.x * blockDim.x + threadIdx.x;
    if (bc >= BCm) return;
    const int xd = g_reg[0], ys = g_reg[1], yd = g_reg[2];
    float area = (float)(xd * (yd - ys));
    if (area < 1.0f) area = 1.0f;
    const float* p = x + (size_t)bc * HWm;
    float s = 0.0f;
    for (int h = 0; h < xd; h++)
        for (int w = ys; w < yd; w++)
            s += p[h * Wm + w];
    g_pooled[bc] = s / area;
}

// ---------------- K5: pooled @ w_fc ----------------------------------------
__global__ void k_fc(const float* __restrict__ wfc, float* __restrict__ out) {
    const int b = blockIdx.x / NCLS;
    const int k = blockIdx.x % NCLS;
    const int tid = threadIdx.x;          // 128
    float s = 0.0f;
    for (int c = tid; c < Cm; c += 128)
        s += g_pooled[b * Cm + c] * wfc[c * NCLS + k];
    __shared__ float red[128];
    red[tid] = s;
    __syncthreads();
    #pragma unroll
    for (int o = 64; o; o >>= 1) {
        if (tid < o) red[tid] += red[tid + o];
        __syncthreads();
    }
    if (tid == 0) out[blockIdx.x] = red[0];
}

// ---------------- launch ----------------------------------------------------
extern "C" void kernel_launch(void* const* d_in, const int* in_sizes, int n_in,
                              void* d_out, int out_size) {
    const float* x   = (const float*)d_in[0];
    const float* wfc = (const float*)d_in[1];
    if (n_in >= 2 && in_sizes[0] == Cm * NCLS) {  // defensive input-order check
        x   = (const float*)d_in[1];
        wfc = (const float*)d_in[0];
    }
    float* out = (float*)d_out;

    const int smem_hist = 4 * NB * 32 * (int)sizeof(unsigned int);  // 128 KB
    const int smem_eklm = NB * 57 * (int)sizeof(float);             // ~58 KB
    cudaFuncSetAttribute(k_hist, cudaFuncAttributeMaxDynamicSharedMemorySize, smem_hist);
    cudaFuncSetAttribute(k_eklm, cudaFuncAttributeMaxDynamicSharedMemorySize, smem_eklm);

    k_hist <<<dim3(28, NCH), 128, smem_hist>>>(x);
    k_integ<<<NB, 256>>>();
    k_eklm <<<1, 256, smem_eklm>>>();
    k_pool <<<(BCm + 255) / 256, 256>>>(x);
    k_fc   <<<Bm * NCLS, 128>>>(wfc, out);
}

// round 2
// speedup vs baseline: 1.6763x; 1.6763x over previous
#include <cuda_runtime.h>
#include <cstdint>
#include <cstdio>

#define Bm   8
#define Cm   1024
#define BCm  8192
#define Hm   56
#define Wm   56
#define HWm  3136
#define NB   256
#define NCH  12
#define CHUNK 683        /* ceil(8192/12); last chunk = 679 */
#define NCLS 30
#define WPB  6           /* warps per hist block */

// ---------------- device scratch (static: no allocations allowed) ----------
// packed: word holds counts for bin b (lo16) and b+128 (hi16)
__device__ unsigned int g_scratch[(size_t)NCH * 128 * HWm];  // ~19 MB, [chunk][bin128][cell]
__device__ float        g_integ[(size_t)NB * HWm];           // 3.2 MB, [bin][cell]
__device__ int          g_reg[4];                            // xd, ys, yd
__device__ float        g_pooled[BCm];

// ---------------- K1: per-chunk per-cell histograms ------------------------
// Grid (17, NCH), block 192 (6 warps), 96 KB smem -> 2 blocks/SM, 12 warps/SM.
// Each LANE owns one spatial cell; private 128-word packed hist column at
// hist[word*32+lane] -> bank == lane -> conflict-free, atomic-free RMW.
__global__ void k_hist(const float* __restrict__ x) {
    extern __shared__ unsigned int sm[];
    const int tid  = threadIdx.x;
    const int warp = tid >> 5;
    const int lane = tid & 31;
    unsigned int* hist = sm + warp * (128 * 32);

    const int wg = blockIdx.x * WPB + warp;     // warp-group 0..97 (98 = 3136/32)
    if (wg >= 98) return;
    const int cell = wg * 32 + lane;            // always < 3136

    #pragma unroll 8
    for (int b = 0; b < 128; b++) hist[b * 32 + lane] = 0u;

    const int bc0 = blockIdx.y * CHUNK;
    const int bc1 = min(BCm, bc0 + CHUNK);

    const float* p = x + cell;
    int bc = bc0;
    for (; bc + 16 <= bc1; bc += 16) {
        float v[16];
        #pragma unroll
        for (int j = 0; j < 16; j++) v[j] = p[(size_t)(bc + j) * HWm];
        #pragma unroll
        for (int j = 0; j < 16; j++) {
            float vv = v[j];
            if (vv >= 0.0f && vv <= 1.0f) {
                int bi = min((int)(vv * 256.0f), 255);
                hist[(bi & 127) * 32 + lane] += (bi < 128) ? 1u : 65536u;
            }
        }
    }
    for (; bc < bc1; bc++) {
        float vv = p[(size_t)bc * HWm];
        if (vv >= 0.0f && vv <= 1.0f) {
            int bi = min((int)(vv * 256.0f), 255);
            hist[(bi & 127) * 32 + lane] += (bi < 128) ? 1u : 65536u;
        }
    }

    // store packed: scratch[chunk][bin128][cell] — coalesced across lanes
    unsigned int* dst = g_scratch + (size_t)blockIdx.y * 128 * HWm + cell;
    #pragma unroll 4
    for (int b = 0; b < 128; b++)
        dst[(size_t)b * HWm] = hist[b * 32 + lane];
}

// ---------------- K2: merge chunks (unpack) + 2D prefix per bin ------------
// Grid 256 (one block per bin), block 256 threads.
__global__ void k_integ() {
    __shared__ float buf[Hm * 57];   // padded stride 57 -> conflict-free cumsums
    const int bin  = blockIdx.x;
    const int b128 = bin & 127;
    const int hi   = bin >> 7;
    const int tid  = threadIdx.x;

    for (int cell = tid; cell < HWm; cell += 256) {
        unsigned int a = 0;
        #pragma unroll
        for (int ch = 0; ch < NCH; ch++) {
            unsigned int w = g_scratch[((size_t)ch * 128 + b128) * HWm + cell];
            a += hi ? (w >> 16) : (w & 0xFFFFu);
        }
        buf[(cell / Wm) * 57 + (cell % Wm)] = (float)a;
    }
    __syncthreads();
    if (tid < Hm) {                  // cumsum along w
        float r = 0.0f;
        for (int w = 0; w < Wm; w++) { r += buf[tid * 57 + w]; buf[tid * 57 + w] = r; }
    }
    __syncthreads();
    if (tid < Wm) {                  // cumsum along h
        float r = 0.0f;
        for (int h = 0; h < Hm; h++) { r += buf[h * 57 + tid]; buf[h * 57 + tid] = r; }
    }
    __syncthreads();
    for (int cell = tid; cell < HWm; cell += 256)
        g_integ[(size_t)bin * HWm + cell] = buf[(cell / Wm) * 57 + (cell % Wm)];
}

// ---------------- K3: EKLM (single block) ----------------------------------
__device__ __forceinline__ float wredsum(float v) {
    #pragma unroll
    for (int o = 16; o; o >>= 1) v += __shfl_xor_sync(0xffffffffu, v, o);
    return v;
}

// entropy of region [0:xd, ys:yd]; warp-collective; xs==0 so 2 lookups/bin.
__device__ float ent_region(int xd, int ys, int yd, int lane) {
    const int cA = (xd - 1) * Wm + (yd - 1);
    const int cB = (ys > 0) ? ((xd - 1) * Wm + (ys - 1)) : -1;
    float hv[8];
    float S = 0.0f;
    #pragma unroll
    for (int k = 0; k < 8; k++) {
        int b = k * 32 + lane;
        float a  = g_integ[(size_t)b * HWm + cA];
        float bb = (cB >= 0) ? g_integ[(size_t)b * HWm + cB] : 0.0f;
        hv[k] = a - bb;
        S += hv[k];
    }
    S = wredsum(S);
    float e = 0.0f;
    #pragma unroll
    for (int k = 0; k < 8; k++) {
        float pp = hv[k] / S;
        e -= pp * __log2f(pp + 1e-9f);
    }
    return wredsum(e);
}

__global__ void k_eklm() {
    extern __shared__ float sh[];            // NB*57 floats (row h=0 of integ)
    __shared__ float enty[Wm];
    __shared__ int   s_ys0;
    const int tid  = threadIdx.x;
    const int lane = tid & 31;
    const int warp = tid >> 5;

    for (int i = tid; i < NB * Wm; i += blockDim.x) {
        int b = i / Wm, w = i % Wm;
        sh[b * 57 + w] = g_integ[(size_t)b * HWm + w];
    }
    __syncthreads();

    // per-column entropies at h==0 (warp per column)
    for (int w = warp; w < Wm; w += 8) {
        float hv[8];
        float S = 0.0f;
        #pragma unroll
        for (int k = 0; k < 8; k++) {
            int b = k * 32 + lane;
            float a  = sh[b * 57 + w];
            float bb = (w > 0) ? sh[b * 57 + w - 1] : 0.0f;
            hv[k] = a - bb;
            S += hv[k];
        }
        S = wredsum(S);
        float e = 0.0f;
        #pragma unroll
        for (int k = 0; k < 8; k++) {
            float pp = hv[k] / S;
            e -= pp * __log2f(pp + 1e-9f);
        }
        e = wredsum(e);
        if (lane == 0) enty[w] = e;
    }
    __syncthreads();

    if (tid == 0) {                          // argmax, first-occurrence
        float best = enty[0];
        int bi = 0;
        for (int w = 1; w < Wm; w++)
            if (enty[w] > best) { best = enty[w]; bi = w; }
        s_ys0 = bi;
    }
    __syncthreads();

    if (warp == 0) {
        const int ys0 = s_ys0;
        const float total = ent_region(Hm, 0, Wm, lane);
        int xd = 1, ys = ys0, yd = ys0 + 1;
        float Ts = ent_region(xd, ys, yd, lane) / total;
        bool done = false;
        int guard = 0;
        while (Ts < 0.9f && !done && guard < 256) {
            guard++;
            float ec = ent_region(xd, ys, yd, lane);
            bool c1 = (xd + 1 < Hm) && (ent_region(xd + 1, ys, yd, lane) > ec);
            bool c2 = !c1 && (ys - 1 >= 0) && (ent_region(xd, ys - 1, yd, lane) > ec);
            bool c3 = !c1 && !c2 && (yd + 1 < Wm) && (ent_region(xd, ys, yd + 1, lane) > ec);
            if (c1) xd++;
            else if (c2) ys--;
            else if (c3) yd++;
            done = !(c1 || c2 || c3);
            Ts = ent_region(xd, ys, yd, lane) / total;
        }
        if (lane == 0) { g_reg[0] = xd; g_reg[1] = ys; g_reg[2] = yd; }
    }
}

// ---------------- K4: region mean-pool (warp per bc, coalesced) ------------
__global__ void k_pool(const float* __restrict__ x) {
    const int warp = threadIdx.x >> 5;
    const int lane = threadIdx.x & 31;
    const int bc = blockIdx.x * 8 + warp;
    if (bc >= BCm) return;
    const int xd = g_reg[0], ys = g_reg[1], yd = g_reg[2];
    float area = (float)(xd * (yd - ys));
    if (area < 1.0f) area = 1.0f;
    const float* p = x + (size_t)bc * HWm;
    float s = 0.0f;
    for (int h = 0; h < xd; h++)
        for (int w = ys + lane; w < yd; w += 32)
            s += p[h * Wm + w];
    s = wredsum(s);
    if (lane == 0) g_pooled[bc] = s / area;
}

// ---------------- K5: pooled @ w_fc ----------------------------------------
__global__ void k_fc(const float* __restrict__ wfc, float* __restrict__ out) {
    const int b = blockIdx.x / NCLS;
    const int k = blockIdx.x % NCLS;
    const int tid = threadIdx.x;          // 128
    float s = 0.0f;
    for (int c = tid; c < Cm; c += 128)
        s += g_pooled[b * Cm + c] * wfc[c * NCLS + k];
    __shared__ float red[128];
    red[tid] = s;
    __syncthreads();
    #pragma unroll
    for (int o = 64; o; o >>= 1) {
        if (tid < o) red[tid] += red[tid + o];
        __syncthreads();
    }
    if (tid == 0) out[blockIdx.x] = red[0];
}

// ---------------- launch ----------------------------------------------------
extern "C" void kernel_launch(void* const* d_in, const int* in_sizes, int n_in,
                              void* d_out, int out_size) {
    const float* x   = (const float*)d_in[0];
    const float* wfc = (const float*)d_in[1];
    if (n_in >= 2 && in_sizes[0] == Cm * NCLS) {  // defensive input-order check
        x   = (const float*)d_in[1];
        wfc = (const float*)d_in[0];
    }
    float* out = (float*)d_out;

    const int smem_hist = WPB * 128 * 32 * (int)sizeof(unsigned int);  // 96 KB
    const int smem_eklm = NB * 57 * (int)sizeof(float);                // ~58 KB
    cudaFuncSetAttribute(k_hist, cudaFuncAttributeMaxDynamicSharedMemorySize, smem_hist);
    cudaFuncSetAttribute(k_eklm, cudaFuncAttributeMaxDynamicSharedMemorySize, smem_eklm);

    k_hist <<<dim3(17, NCH), WPB * 32, smem_hist>>>(x);
    k_integ<<<NB, 256>>>();
    k_eklm <<<1, 256, smem_eklm>>>();
    k_pool <<<(BCm + 7) / 8, 256>>>(x);
    k_fc   <<<Bm * NCLS, 128>>>(wfc, out);
}

// round 5
// speedup vs baseline: 1.8630x; 1.1114x over previous
#include <cuda_runtime.h>
#include <cstdint>
#include <cstdio>

#define Bm   8
#define Cm   1024
#define BCm  8192
#define Hm   56
#define Wm   56
#define HWm  3136
#define NB   256
#define NCH  33
#define CHUNK 249        /* <=255 guarantees 8-bit per-chunk counts never overflow */
#define NCLS 30
#define WPB  8           /* warps per hist block */

// ---------------- device scratch (static: no allocations allowed) ----------
// packed: word wd holds 8-bit counts for bins {wd, wd+64, wd+128, wd+192}
__device__ unsigned int g_scratch[(size_t)NCH * 64 * HWm];   // ~26.5 MB, [chunk][word][cell]
__device__ float        g_integ[(size_t)NB * HWm];           // 3.2 MB, [bin][cell]
__device__ int          g_reg[4];                            // xd, ys, yd
__device__ float        g_pooled[BCm];

// ---------------- dummy kernels to shift the ncu capture window ------------
__global__ void k_nop() {}

// ---------------- K1: per-chunk per-cell histograms ------------------------
// Grid (13, NCH), block 256 (8 warps), 64 KB smem -> 3 blocks/SM, 24 warps/SM.
// Each LANE owns one spatial cell; private 64-word (4x8-bit packed) hist
// column at hist[word*32+lane] -> bank == lane -> conflict-free, atomic-free.
__global__ void k_hist(const float* __restrict__ x) {
    extern __shared__ unsigned int sm[];
    const int tid  = threadIdx.x;
    const int warp = tid >> 5;
    const int lane = tid & 31;
    unsigned int* hist = sm + warp * (64 * 32);

    const int wg = blockIdx.x * WPB + warp;     // warp-group 0..103 (98 used)
    if (wg >= 98) return;
    const int cell = wg * 32 + lane;            // < 3136

    #pragma unroll 8
    for (int b = 0; b < 64; b++) hist[b * 32 + lane] = 0u;

    const int bc0 = blockIdx.y * CHUNK;
    const int bc1 = min(BCm, bc0 + CHUNK);

    const float* p = x + cell;
    int bc = bc0;
    #define PROC(vv) do {                                               \
        if ((vv) >= 0.0f && (vv) <= 1.0f) {                             \
            int bi = min((int)((vv) * 256.0f), 255);                    \
            hist[(bi & 63) * 32 + lane] += 1u << ((bi >> 6) * 8);       \
        } } while (0)
    for (; bc + 16 <= bc1; bc += 16) {
        float v[16];
        #pragma unroll
        for (int j = 0; j < 16; j++) v[j] = __ldcs(p + (size_t)(bc + j) * HWm);
        #pragma unroll
        for (int j = 0; j < 16; j++) PROC(v[j]);
    }
    for (; bc < bc1; bc++) {
        float vv = __ldcs(p + (size_t)bc * HWm);
        PROC(vv);
    }
    #undef PROC

    // store packed: scratch[chunk][word][cell] — coalesced across lanes
    unsigned int* dst = g_scratch + (size_t)blockIdx.y * 64 * HWm + cell;
    #pragma unroll 4
    for (int b = 0; b < 64; b++)
        dst[(size_t)b * HWm] = hist[b * 32 + lane];
}

// ---------------- K2: merge chunks (unpack 4 bins/word) + 2D prefix --------
// Grid 64 (one block per packed word), block 256. Scratch read exactly once.
__global__ void k_integ() {
    __shared__ float buf[4][Hm * 57];   // 4 bin-planes, padded stride 57
    const int wd  = blockIdx.x;         // word 0..63 -> bins p*64+wd
    const int tid = threadIdx.x;

    for (int cell = tid; cell < HWm; cell += 256) {
        unsigned int a0 = 0, a1 = 0;    // 16-bit lane sums (max 8217 < 65536)
        #pragma unroll 3
        for (int ch = 0; ch < NCH; ch++) {
            unsigned int w = g_scratch[((size_t)ch * 64 + wd) * HWm + cell];
            a0 += w & 0x00FF00FFu;
            a1 += (w >> 8) & 0x00FF00FFu;
        }
        const int idx = (cell / Wm) * 57 + (cell % Wm);
        buf[0][idx] = (float)(a0 & 0xFFFFu);
        buf[1][idx] = (float)(a1 & 0xFFFFu);
        buf[2][idx] = (float)(a0 >> 16);
        buf[3][idx] = (float)(a1 >> 16);
    }
    __syncthreads();
    if (tid < 4 * Hm) {                 // cumsum along w: (plane, row)
        const int p = tid / Hm, r = tid % Hm;
        float acc = 0.0f;
        for (int w = 0; w < Wm; w++) { acc += buf[p][r * 57 + w]; buf[p][r * 57 + w] = acc; }
    }
    __syncthreads();
    if (tid < 4 * Wm) {                 // cumsum along h: (plane, col)
        const int p = tid / Wm, c = tid % Wm;
        float acc = 0.0f;
        for (int h = 0; h < Hm; h++) { acc += buf[p][h * 57 + c]; buf[p][h * 57 + c] = acc; }
    }
    __syncthreads();
    for (int cell = tid; cell < HWm; cell += 256) {
        const int idx = (cell / Wm) * 57 + (cell % Wm);
        #pragma unroll
        for (int p = 0; p < 4; p++)
            g_integ[(size_t)(p * 64 + wd) * HWm + cell] = buf[p][idx];
    }
}

// ---------------- K3: EKLM (single block) ----------------------------------
__device__ __forceinline__ float wredsum(float v) {
    #pragma unroll
    for (int o = 16; o; o >>= 1) v += __shfl_xor_sync(0xffffffffu, v, o);
    return v;
}

// entropy of region [0:xd, ys:yd]; warp-collective; xs==0 so 2 lookups/bin.
__device__ float ent_region(int xd, int ys, int yd, int lane) {
    const int cA = (xd - 1) * Wm + (yd - 1);
    const int cB = (ys > 0) ? ((xd - 1) * Wm + (ys - 1)) : -1;
    float hv[8];
    float S = 0.0f;
    #pragma unroll
    for (int k = 0; k < 8; k++) {
        int b = k * 32 + lane;
        float a  = g_integ[(size_t)b * HWm + cA];
        float bb = (cB >= 0) ? g_integ[(size_t)b * HWm + cB] : 0.0f;
        hv[k] = a - bb;
        S += hv[k];
    }
    S = wredsum(S);
    float e = 0.0f;
    #pragma unroll
    for (int k = 0; k < 8; k++) {
        float pp = hv[k] / S;
        e -= pp * __log2f(pp + 1e-9f);
    }
    return wredsum(e);
}

__global__ void k_eklm() {
    extern __shared__ float sh[];            // NB*57 floats (row h=0 of integ)
    __shared__ float enty[Wm];
    __shared__ int   s_ys0;
    const int tid  = threadIdx.x;
    const int lane = tid & 31;
    const int warp = tid >> 5;

    for (int i = tid; i < NB * Wm; i += blockDim.x) {
        int b = i / Wm, w = i % Wm;
        sh[b * 57 + w] = g_integ[(size_t)b * HWm + w];
    }
    __syncthreads();

    // per-column entropies at h==0 (warp per column)
    for (int w = warp; w < Wm; w += 8) {
        float hv[8];
        float S = 0.0f;
        #pragma unroll
        for (int k = 0; k < 8; k++) {
            int b = k * 32 + lane;
            float a  = sh[b * 57 + w];
            float bb = (w > 0) ? sh[b * 57 + w - 1] : 0.0f;
            hv[k] = a - bb;
            S += hv[k];
        }
        S = wredsum(S);
        float e = 0.0f;
        #pragma unroll
        for (int k = 0; k < 8; k++) {
            float pp = hv[k] / S;
            e -= pp * __log2f(pp + 1e-9f);
        }
        e = wredsum(e);
        if (lane == 0) enty[w] = e;
    }
    __syncthreads();

    if (tid == 0) {                          // argmax, first-occurrence
        float best = enty[0];
        int bi = 0;
        for (int w = 1; w < Wm; w++)
            if (enty[w] > best) { best = enty[w]; bi = w; }
        s_ys0 = bi;
    }
    __syncthreads();

    if (warp == 0) {
        const int ys0 = s_ys0;
        const float total = ent_region(Hm, 0, Wm, lane);
        int xd = 1, ys = ys0, yd = ys0 + 1;
        float Ts = ent_region(xd, ys, yd, lane) / total;
        bool done = false;
        int guard = 0;
        while (Ts < 0.9f && !done && guard < 256) {
            guard++;
            float ec = ent_region(xd, ys, yd, lane);
            bool c1 = (xd + 1 < Hm) && (ent_region(xd + 1, ys, yd, lane) > ec);
            bool c2 = !c1 && (ys - 1 >= 0) && (ent_region(xd, ys - 1, yd, lane) > ec);
            bool c3 = !c1 && !c2 && (yd + 1 < Wm) && (ent_region(xd, ys, yd + 1, lane) > ec);
            if (c1) xd++;
            else if (c2) ys--;
            else if (c3) yd++;
            done = !(c1 || c2 || c3);
            Ts = ent_region(xd, ys, yd, lane) / total;
        }
        if (lane == 0) { g_reg[0] = xd; g_reg[1] = ys; g_reg[2] = yd; }
    }
}

// ---------------- K4: region mean-pool (warp per bc, coalesced) ------------
__global__ void k_pool(const float* __restrict__ x) {
    const int warp = threadIdx.x >> 5;
    const int lane = threadIdx.x & 31;
    const int bc = blockIdx.x * 8 + warp;
    if (bc >= BCm) return;
    const int xd = g_reg[0], ys = g_reg[1], yd = g_reg[2];
    float area = (float)(xd * (yd - ys));
    if (area < 1.0f) area = 1.0f;
    const float* p = x + (size_t)bc * HWm;
    float s = 0.0f;
    for (int h = 0; h < xd; h++)
        for (int w = ys + lane; w < yd; w += 32)
            s += p[h * Wm + w];
    s = wredsum(s);
    if (lane == 0) g_pooled[bc] = s / area;
}

// ---------------- K5: pooled @ w_fc ----------------------------------------
__global__ void k_fc(const float* __restrict__ wfc, float* __restrict__ out) {
    const int b = blockIdx.x / NCLS;
    const int k = blockIdx.x % NCLS;
    const int tid = threadIdx.x;          // 128
    float s = 0.0f;
    for (int c = tid; c < Cm; c += 128)
        s += g_pooled[b * Cm + c] * wfc[c * NCLS + k];
    __shared__ float red[128];
    red[tid] = s;
    __syncthreads();
    #pragma unroll
    for (int o = 64; o; o >>= 1) {
        if (tid < o) red[tid] += red[tid + o];
        __syncthreads();
    }
    if (tid == 0) out[blockIdx.x] = red[0];
}

// ---------------- launch ----------------------------------------------------
extern "C" void kernel_launch(void* const* d_in, const int* in_sizes, int n_in,
                              void* d_out, int out_size) {
    const float* x   = (const float*)d_in[0];
    const float* wfc = (const float*)d_in[1];
    if (n_in >= 2 && in_sizes[0] == Cm * NCLS) {  // defensive input-order check
        x   = (const float*)d_in[1];
        wfc = (const float*)d_in[0];
    }
    float* out = (float*)d_out;

    const int smem_hist = WPB * 64 * 32 * (int)sizeof(unsigned int);   // 64 KB
    const int smem_eklm = NB * 57 * (int)sizeof(float);                // ~58 KB
    cudaFuncSetAttribute(k_hist, cudaFuncAttributeMaxDynamicSharedMemorySize, smem_hist);
    cudaFuncSetAttribute(k_eklm, cudaFuncAttributeMaxDynamicSharedMemorySize, smem_eklm);

    // shift fixed ncu window (-s 5 -c 1) so it lands on k_hist
    k_nop  <<<1, 32>>>();
    k_nop  <<<1, 32>>>();
    k_nop  <<<1, 32>>>();

    k_hist <<<dim3(13, NCH), WPB * 32, smem_hist>>>(x);
    k_integ<<<64, 256>>>();
    k_eklm <<<1, 256, smem_eklm>>>();
    k_pool <<<(BCm + 7) / 8, 256>>>(x);
    k_fc   <<<Bm * NCLS, 128>>>(wfc, out);
}

// round 7
// speedup vs baseline: 2.7402x; 1.4709x over previous
#include <cuda_runtime.h>
#include <cstdint>
#include <cstdio>

#define Bm   8
#define Cm   1024
#define BCm  8192
#define Hm   56
#define Wm   56
#define HWm  3136
#define NB   256
#define NCH  33
#define CHUNK 249        /* <=255 guarantees 8-bit per-chunk counts never overflow */
#define NCLS 30
#define WPB  4           /* warps per hist block: 32KB smem -> 7 blocks/SM = 28 warps */

// ---------------- device scratch (static: no allocations allowed) ----------
// packed: word wd holds 8-bit counts for bins {wd, wd+64, wd+128, wd+192}
__device__ unsigned int g_scratch[(size_t)NCH * 64 * HWm];   // ~26.5 MB, [chunk][word][cell]
__device__ float        g_integ[(size_t)NB * HWm];           // 3.2 MB, [bin][cell]
__device__ int          g_reg[4];                            // xd, ys, yd
__device__ float        g_pooled[BCm];

// ---------------- dummy kernels to shift the ncu capture window ------------
__global__ void k_nop() {}

// ---------------- K1: per-chunk per-cell histograms ------------------------
// Grid (25, NCH), block 128 (4 warps), 32 KB smem -> 7 blocks/SM, 28 warps/SM.
// Each LANE owns one spatial cell; private 64-word (4x8-bit packed) hist
// column at hist[word*32+lane] -> bank == lane -> conflict-free, atomic-free.
__global__ void k_hist(const float* __restrict__ x) {
    extern __shared__ unsigned int sm[];
    const int tid  = threadIdx.x;
    const int warp = tid >> 5;
    const int lane = tid & 31;
    unsigned int* hist = sm + warp * (64 * 32);

    const int wg = blockIdx.x * WPB + warp;     // warp-group, 98 used
    if (wg >= 98) return;
    const int cell = wg * 32 + lane;            // < 3136

    #pragma unroll 8
    for (int b = 0; b < 64; b++) hist[b * 32 + lane] = 0u;

    const int bc0 = blockIdx.y * CHUNK;
    const int bc1 = min(BCm, bc0 + CHUNK);

    const float* p = x + cell;
    int bc = bc0;
    #define PROC(vv) do {                                               \
        if ((vv) >= 0.0f && (vv) <= 1.0f) {                             \
            int bi = min((int)((vv) * 256.0f), 255);                    \
            hist[(bi & 63) * 32 + lane] += 1u << ((bi >> 6) * 8);       \
        } } while (0)
    for (; bc + 16 <= bc1; bc += 16) {
        float v[16];
        #pragma unroll
        for (int j = 0; j < 16; j++) v[j] = __ldcs(p + (size_t)(bc + j) * HWm);
        #pragma unroll
        for (int j = 0; j < 16; j++) PROC(v[j]);
    }
    for (; bc < bc1; bc++) {
        float vv = __ldcs(p + (size_t)bc * HWm);
        PROC(vv);
    }
    #undef PROC

    // store packed: scratch[chunk][word][cell] — coalesced across lanes
    unsigned int* dst = g_scratch + (size_t)blockIdx.y * 64 * HWm + cell;
    #pragma unroll 4
    for (int b = 0; b < 64; b++)
        dst[(size_t)b * HWm] = hist[b * 32 + lane];
}

// ---------------- K1b: high-parallelism chunk merge ------------------------
// Grid (13, 64), block 256: one thread per (word, cell). Fully unrolled
// 33-chunk sum -> MLP~33/thread, thousands of warps: BW-bound, ~6us.
// Writes unpacked per-bin counts (as float) into g_integ.
__global__ void k_merge() {
    const int cell = blockIdx.x * 256 + threadIdx.x;
    const int wd   = blockIdx.y;               // packed word 0..63
    if (cell >= HWm) return;
    unsigned int a0 = 0, a1 = 0;               // 16-bit lane sums (max 8217)
    #pragma unroll
    for (int ch = 0; ch < NCH; ch++) {
        unsigned int w = __ldcs(&g_scratch[((size_t)ch * 64 + wd) * HWm + cell]);
        a0 += w & 0x00FF00FFu;
        a1 += (w >> 8) & 0x00FF00FFu;
    }
    g_integ[(size_t)(  0 + wd) * HWm + cell] = (float)(a0 & 0xFFFFu);
    g_integ[(size_t)( 64 + wd) * HWm + cell] = (float)(a1 & 0xFFFFu);
    g_integ[(size_t)(128 + wd) * HWm + cell] = (float)(a0 >> 16);
    g_integ[(size_t)(192 + wd) * HWm + cell] = (float)(a1 >> 16);
}

// ---------------- K2: in-place 2D prefix per bin ---------------------------
// Grid 64 (4 consecutive bins per block), block 256. All traffic L2-resident.
__global__ void k_integ() {
    __shared__ float buf[4][Hm * 57];   // 4 bin-planes, padded stride 57
    const int b0  = blockIdx.x * 4;
    const int tid = threadIdx.x;

    for (int cell = tid; cell < HWm; cell += 256) {
        const int idx = (cell / Wm) * 57 + (cell % Wm);
        #pragma unroll
        for (int p = 0; p < 4; p++)
            buf[p][idx] = g_integ[(size_t)(b0 + p) * HWm + cell];
    }
    __syncthreads();
    if (tid < 4 * Hm) {                 // cumsum along w: (plane, row)
        const int p = tid / Hm, r = tid % Hm;
        float acc = 0.0f;
        for (int w = 0; w < Wm; w++) { acc += buf[p][r * 57 + w]; buf[p][r * 57 + w] = acc; }
    }
    __syncthreads();
    if (tid < 4 * Wm) {                 // cumsum along h: (plane, col)
        const int p = tid / Wm, c = tid % Wm;
        float acc = 0.0f;
        for (int h = 0; h < Hm; h++) { acc += buf[p][h * 57 + c]; buf[p][h * 57 + c] = acc; }
    }
    __syncthreads();
    for (int cell = tid; cell < HWm; cell += 256) {
        const int idx = (cell / Wm) * 57 + (cell % Wm);
        #pragma unroll
        for (int p = 0; p < 4; p++)
            g_integ[(size_t)(b0 + p) * HWm + cell] = buf[p][idx];
    }
}

// ---------------- K3: EKLM (single block) ----------------------------------
__device__ __forceinline__ float wredsum(float v) {
    #pragma unroll
    for (int o = 16; o; o >>= 1) v += __shfl_xor_sync(0xffffffffu, v, o);
    return v;
}

// entropy of region [0:xd, ys:yd]; warp-collective; xs==0 so 2 lookups/bin.
__device__ float ent_region(int xd, int ys, int yd, int lane) {
    const int cA = (xd - 1) * Wm + (yd - 1);
    const int cB = (ys > 0) ? ((xd - 1) * Wm + (ys - 1)) : -1;
    float hv[8];
    float S = 0.0f;
    #pragma unroll
    for (int k = 0; k < 8; k++) {
        int b = k * 32 + lane;
        float a  = g_integ[(size_t)b * HWm + cA];
        float bb = (cB >= 0) ? g_integ[(size_t)b * HWm + cB] : 0.0f;
        hv[k] = a - bb;
        S += hv[k];
    }
    S = wredsum(S);
    float e = 0.0f;
    #pragma unroll
    for (int k = 0; k < 8; k++) {
        float pp = hv[k] / S;
        e -= pp * __log2f(pp + 1e-9f);
    }
    return wredsum(e);
}

__global__ void k_eklm() {
    extern __shared__ float sh[];            // NB*57 floats (row h=0 of integ)
    __shared__ float enty[Wm];
    __shared__ int   s_ys0;
    const int tid  = threadIdx.x;
    const int lane = tid & 31;
    const int warp = tid >> 5;

    for (int i = tid; i < NB * Wm; i += blockDim.x) {
        int b = i / Wm, w = i % Wm;
        sh[b * 57 + w] = g_integ[(size_t)b * HWm + w];
    }
    __syncthreads();

    // per-column entropies at h==0 (warp per column)
    for (int w = warp; w < Wm; w += 8) {
        float hv[8];
        float S = 0.0f;
        #pragma unroll
        for (int k = 0; k < 8; k++) {
            int b = k * 32 + lane;
            float a  = sh[b * 57 + w];
            float bb = (w > 0) ? sh[b * 57 + w - 1] : 0.0f;
            hv[k] = a - bb;
            S += hv[k];
        }
        S = wredsum(S);
        float e = 0.0f;
        #pragma unroll
        for (int k = 0; k < 8; k++) {
            float pp = hv[k] / S;
            e -= pp * __log2f(pp + 1e-9f);
        }
        e = wredsum(e);
        if (lane == 0) enty[w] = e;
    }
    __syncthreads();

    if (tid == 0) {                          // argmax, first-occurrence
        float best = enty[0];
        int bi = 0;
        for (int w = 1; w < Wm; w++)
            if (enty[w] > best) { best = enty[w]; bi = w; }
        s_ys0 = bi;
    }
    __syncthreads();

    if (warp == 0) {
        const int ys0 = s_ys0;
        const float total = ent_region(Hm, 0, Wm, lane);
        int xd = 1, ys = ys0, yd = ys0 + 1;
        float Ts = ent_region(xd, ys, yd, lane) / total;
        bool done = false;
        int guard = 0;
        while (Ts < 0.9f && !done && guard < 256) {
            guard++;
            float ec = ent_region(xd, ys, yd, lane);
            bool c1 = (xd + 1 < Hm) && (ent_region(xd + 1, ys, yd, lane) > ec);
            bool c2 = !c1 && (ys - 1 >= 0) && (ent_region(xd, ys - 1, yd, lane) > ec);
            bool c3 = !c1 && !c2 && (yd + 1 < Wm) && (ent_region(xd, ys, yd + 1, lane) > ec);
            if (c1) xd++;
            else if (c2) ys--;
            else if (c3) yd++;
            done = !(c1 || c2 || c3);
            Ts = ent_region(xd, ys, yd, lane) / total;
        }
        if (lane == 0) { g_reg[0] = xd; g_reg[1] = ys; g_reg[2] = yd; }
    }
}

// ---------------- K4: region mean-pool (warp per bc, coalesced) ------------
__global__ void k_pool(const float* __restrict__ x) {
    const int warp = threadIdx.x >> 5;
    const int lane = threadIdx.x & 31;
    const int bc = blockIdx.x * 8 + warp;
    if (bc >= BCm) return;
    const int xd = g_reg[0], ys = g_reg[1], yd = g_reg[2];
    float area = (float)(xd * (yd - ys));
    if (area < 1.0f) area = 1.0f;
    const float* p = x + (size_t)bc * HWm;
    float s = 0.0f;
    for (int h = 0; h < xd; h++)
        for (int w = ys + lane; w < yd; w += 32)
            s += p[h * Wm + w];
    s = wredsum(s);
    if (lane == 0) g_pooled[bc] = s / area;
}

// ---------------- K5: pooled @ w_fc ----------------------------------------
__global__ void k_fc(const float* __restrict__ wfc, float* __restrict__ out) {
    const int b = blockIdx.x / NCLS;
    const int k = blockIdx.x % NCLS;
    const int tid = threadIdx.x;          // 128
    float s = 0.0f;
    for (int c = tid; c < Cm; c += 128)
        s += g_pooled[b * Cm + c] * wfc[c * NCLS + k];
    __shared__ float red[128];
    red[tid] = s;
    __syncthreads();
    #pragma unroll
    for (int o = 64; o; o >>= 1) {
        if (tid < o) red[tid] += red[tid + o];
        __syncthreads();
    }
    if (tid == 0) out[blockIdx.x] = red[0];
}

// ---------------- launch ----------------------------------------------------
extern "C" void kernel_launch(void* const* d_in, const int* in_sizes, int n_in,
                              void* d_out, int out_size) {
    const float* x   = (const float*)d_in[0];
    const float* wfc = (const float*)d_in[1];
    if (n_in >= 2 && in_sizes[0] == Cm * NCLS) {  // defensive input-order check
        x   = (const float*)d_in[1];
        wfc = (const float*)d_in[0];
    }
    float* out = (float*)d_out;

    const int smem_hist = WPB * 64 * 32 * (int)sizeof(unsigned int);   // 32 KB
    const int smem_eklm = NB * 57 * (int)sizeof(float);                // ~58 KB
    cudaFuncSetAttribute(k_hist, cudaFuncAttributeMaxDynamicSharedMemorySize, smem_hist);
    cudaFuncSetAttribute(k_eklm, cudaFuncAttributeMaxDynamicSharedMemorySize, smem_eklm);

    // 2 nops: profiled launch (index 3) lands on k_merge this round
    k_nop  <<<1, 32>>>();
    k_nop  <<<1, 32>>>();

    k_hist <<<dim3(25, NCH), WPB * 32, smem_hist>>>(x);
    k_merge<<<dim3(13, 64), 256>>>();
    k_integ<<<64, 256>>>();
    k_eklm <<<1, 256, smem_eklm>>>();
    k_pool <<<(BCm + 7) / 8, 256>>>(x);
    k_fc   <<<Bm * NCLS, 128>>>(wfc, out);
}

// round 10
// speedup vs baseline: 2.7837x; 1.0159x over previous
#include <cuda_runtime.h>
#include <cstdint>
#include <cstdio>

#define Bm   8
#define Cm   1024
#define BCm  8192
#define Hm   56
#define Wm   56
#define HWm  3136
#define NB   256
#define NCH  33
#define CHUNK 249        /* <=255 guarantees 8-bit per-chunk counts never overflow */
#define NCLS 30
#define WPB  4           /* warps per hist block: 32KB smem -> 7 blocks/SM = 28 warps */

// ---------------- device scratch (static: no allocations allowed) ----------
// packed: word wd holds 8-bit counts for bins {wd, wd+64, wd+128, wd+192}
__device__ unsigned int g_scratch[(size_t)NCH * 64 * HWm];   // ~26.5 MB, [chunk][word][cell]
__device__ float        g_integ[(size_t)NB * HWm];           // 3.2 MB, [bin][cell]
__device__ int          g_reg[4];                            // xd, ys, yd
__device__ float        g_pooled[BCm];

// ---------------- dummy kernels to shift the ncu capture window ------------
__global__ void k_nop() {}

// ---------------- K1: per-chunk per-cell histograms ------------------------
// Grid (25, NCH), block 128 (4 warps), 32 KB smem -> 7 blocks/SM, 28 warps/SM.
// launch_bounds(128,7): reg cap ~72 so the 16-load batch stays in flight.
// Each LANE owns one spatial cell; private 64-word (4x8-bit packed) hist
// column at hist[word*32+lane] -> bank == lane -> conflict-free, atomic-free.
__global__ void __launch_bounds__(128, 7) k_hist(const float* __restrict__ x) {
    extern __shared__ unsigned int sm[];
    const int tid  = threadIdx.x;
    const int warp = tid >> 5;
    const int lane = tid & 31;
    unsigned int* hist = sm + warp * (64 * 32);

    const int wg = blockIdx.x * WPB + warp;     // warp-group, 98 used
    if (wg >= 98) return;
    const int cell = wg * 32 + lane;            // < 3136

    #pragma unroll 8
    for (int b = 0; b < 64; b++) hist[b * 32 + lane] = 0u;

    const int bc0 = blockIdx.y * CHUNK;
    const int bc1 = min(BCm, bc0 + CHUNK);

    const float* p = x + cell;
    int bc = bc0;
    #define PROC(vv) do {                                               \
        if ((vv) >= 0.0f && (vv) <= 1.0f) {                             \
            int bi = min((int)((vv) * 256.0f), 255);                    \
            hist[(bi & 63) * 32 + lane] += 1u << ((bi >> 6) * 8);       \
        } } while (0)
    for (; bc + 16 <= bc1; bc += 16) {
        float v[16];
        #pragma unroll
        for (int j = 0; j < 16; j++) v[j] = __ldcs(p + (size_t)(bc + j) * HWm);
        #pragma unroll
        for (int j = 0; j < 16; j++) PROC(v[j]);
    }
    for (; bc < bc1; bc++) {
        float vv = __ldcs(p + (size_t)bc * HWm);
        PROC(vv);
    }
    #undef PROC

    // store packed: scratch[chunk][word][cell] — coalesced across lanes
    unsigned int* dst = g_scratch + (size_t)blockIdx.y * 64 * HWm + cell;
    #pragma unroll 4
    for (int b = 0; b < 64; b++)
        dst[(size_t)b * HWm] = hist[b * 32 + lane];
}

// ---------------- K1b: high-parallelism chunk merge ------------------------
// Grid (7, 64), block 256: one thread per (word, cell-pair), uint2 loads.
// launch_bounds(256,3): reg cap ~85 -> full 33-deep load chain in flight.
// Writes unpacked per-bin counts (as float2) into g_integ.
__global__ void __launch_bounds__(256, 3) k_merge() {
    const int pair = blockIdx.x * 256 + threadIdx.x;   // 0..1567
    const int wd   = blockIdx.y;                       // packed word 0..63
    if (pair >= HWm / 2) return;
    const int cell = pair * 2;
    unsigned int a0x = 0, a1x = 0, a0y = 0, a1y = 0;   // 16-bit lane sums
    #pragma unroll
    for (int ch = 0; ch < NCH; ch++) {
        uint2 w = __ldcs((const uint2*)&g_scratch[((size_t)ch * 64 + wd) * HWm + cell]);
        a0x += w.x & 0x00FF00FFu;  a1x += (w.x >> 8) & 0x00FF00FFu;
        a0y += w.y & 0x00FF00FFu;  a1y += (w.y >> 8) & 0x00FF00FFu;
    }
    *(float2*)&g_integ[(size_t)(  0 + wd) * HWm + cell] =
        make_float2((float)(a0x & 0xFFFFu), (float)(a0y & 0xFFFFu));
    *(float2*)&g_integ[(size_t)( 64 + wd) * HWm + cell] =
        make_float2((float)(a1x & 0xFFFFu), (float)(a1y & 0xFFFFu));
    *(float2*)&g_integ[(size_t)(128 + wd) * HWm + cell] =
        make_float2((float)(a0x >> 16), (float)(a0y >> 16));
    *(float2*)&g_integ[(size_t)(192 + wd) * HWm + cell] =
        make_float2((float)(a1x >> 16), (float)(a1y >> 16));
}

// ---------------- K2: in-place 2D prefix per bin ---------------------------
// Grid 64 (4 consecutive bins per block), block 256. All traffic L2-resident.
__global__ void k_integ() {
    __shared__ float buf[4][Hm * 57];   // 4 bin-planes, padded stride 57
    const int b0  = blockIdx.x * 4;
    const int tid = threadIdx.x;

    for (int cell = tid; cell < HWm; cell += 256) {
        const int idx = (cell / Wm) * 57 + (cell % Wm);
        #pragma unroll
        for (int p = 0; p < 4; p++)
            buf[p][idx] = g_integ[(size_t)(b0 + p) * HWm + cell];
    }
    __syncthreads();
    if (tid < 4 * Hm) {                 // cumsum along w: (plane, row)
        const int p = tid / Hm, r = tid % Hm;
        float acc = 0.0f;
        for (int w = 0; w < Wm; w++) { acc += buf[p][r * 57 + w]; buf[p][r * 57 + w] = acc; }
    }
    __syncthreads();
    if (tid < 4 * Wm) {                 // cumsum along h: (plane, col)
        const int p = tid / Wm, c = tid % Wm;
        float acc = 0.0f;
        for (int h = 0; h < Hm; h++) { acc += buf[p][h * 57 + c]; buf[p][h * 57 + c] = acc; }
    }
    __syncthreads();
    for (int cell = tid; cell < HWm; cell += 256) {
        const int idx = (cell / Wm) * 57 + (cell % Wm);
        #pragma unroll
        for (int p = 0; p < 4; p++)
            g_integ[(size_t)(b0 + p) * HWm + cell] = buf[p][idx];
    }
}

// ---------------- K3: EKLM (single block) ----------------------------------
__device__ __forceinline__ float wredsum(float v) {
    #pragma unroll
    for (int o = 16; o; o >>= 1) v += __shfl_xor_sync(0xffffffffu, v, o);
    return v;
}

// entropy of region [0:xd, ys:yd]; warp-collective; xs==0 so 2 lookups/bin.
__device__ float ent_region(int xd, int ys, int yd, int lane) {
    const int cA = (xd - 1) * Wm + (yd - 1);
    const int cB = (ys > 0) ? ((xd - 1) * Wm + (ys - 1)) : -1;
    float hv[8];
    float S = 0.0f;
    #pragma unroll
    for (int k = 0; k < 8; k++) {
        int b = k * 32 + lane;
        float a  = g_integ[(size_t)b * HWm + cA];
        float bb = (cB >= 0) ? g_integ[(size_t)b * HWm + cB] : 0.0f;
        hv[k] = a - bb;
        S += hv[k];
    }
    S = wredsum(S);
    float e = 0.0f;
    #pragma unroll
    for (int k = 0; k < 8; k++) {
        float pp = hv[k] / S;
        e -= pp * __log2f(pp + 1e-9f);
    }
    return wredsum(e);
}

__global__ void k_eklm() {
    extern __shared__ float sh[];            // NB*57 floats (row h=0 of integ)
    __shared__ float enty[Wm];
    __shared__ int   s_ys0;
    const int tid  = threadIdx.x;
    const int lane = tid & 31;
    const int warp = tid >> 5;

    for (int i = tid; i < NB * Wm; i += blockDim.x) {
        int b = i / Wm, w = i % Wm;
        sh[b * 57 + w] = g_integ[(size_t)b * HWm + w];
    }
    __syncthreads();

    // per-column entropies at h==0 (warp per column)
    for (int w = warp; w < Wm; w += 8) {
        float hv[8];
        float S = 0.0f;
        #pragma unroll
        for (int k = 0; k < 8; k++) {
            int b = k * 32 + lane;
            float a  = sh[b * 57 + w];
            float bb = (w > 0) ? sh[b * 57 + w - 1] : 0.0f;
            hv[k] = a - bb;
            S += hv[k];
        }
        S = wredsum(S);
        float e = 0.0f;
        #pragma unroll
        for (int k = 0; k < 8; k++) {
            float pp = hv[k] / S;
            e -= pp * __log2f(pp + 1e-9f);
        }
        e = wredsum(e);
        if (lane == 0) enty[w] = e;
    }
    __syncthreads();

    if (tid == 0) {                          // argmax, first-occurrence
        float best = enty[0];
        int bi = 0;
        for (int w = 1; w < Wm; w++)
            if (enty[w] > best) { best = enty[w]; bi = w; }
        s_ys0 = bi;
    }
    __syncthreads();

    if (warp == 0) {
        const int ys0 = s_ys0;
        const float total = ent_region(Hm, 0, Wm, lane);
        int xd = 1, ys = ys0, yd = ys0 + 1;
        float Ts = ent_region(xd, ys, yd, lane) / total;
        bool done = false;
        int guard = 0;
        while (Ts < 0.9f && !done && guard < 256) {
            guard++;
            float ec = ent_region(xd, ys, yd, lane);
            bool c1 = (xd + 1 < Hm) && (ent_region(xd + 1, ys, yd, lane) > ec);
            bool c2 = !c1 && (ys - 1 >= 0) && (ent_region(xd, ys - 1, yd, lane) > ec);
            bool c3 = !c1 && !c2 && (yd + 1 < Wm) && (ent_region(xd, ys, yd + 1, lane) > ec);
            if (c1) xd++;
            else if (c2) ys--;
            else if (c3) yd++;
            done = !(c1 || c2 || c3);
            Ts = ent_region(xd, ys, yd, lane) / total;
        }
        if (lane == 0) { g_reg[0] = xd; g_reg[1] = ys; g_reg[2] = yd; }
    }
}

// ---------------- K4: region mean-pool (warp per bc, coalesced) ------------
__global__ void k_pool(const float* __restrict__ x) {
    const int warp = threadIdx.x >> 5;
    const int lane = threadIdx.x & 31;
    const int bc = blockIdx.x * 8 + warp;
    if (bc >= BCm) return;
    const int xd = g_reg[0], ys = g_reg[1], yd = g_reg[2];
    float area = (float)(xd * (yd - ys));
    if (area < 1.0f) area = 1.0f;
    const float* p = x + (size_t)bc * HWm;
    float s = 0.0f;
    for (int h = 0; h < xd; h++)
        for (int w = ys + lane; w < yd; w += 32)
            s += p[h * Wm + w];
    s = wredsum(s);
    if (lane == 0) g_pooled[bc] = s / area;
}

// ---------------- K5: pooled @ w_fc ----------------------------------------
__global__ void k_fc(const float* __restrict__ wfc, float* __restrict__ out) {
    const int b = blockIdx.x / NCLS;
    const int k = blockIdx.x % NCLS;
    const int tid = threadIdx.x;          // 128
    float s = 0.0f;
    for (int c = tid; c < Cm; c += 128)
        s += g_pooled[b * Cm + c] * wfc[c * NCLS + k];
    __shared__ float red[128];
    red[tid] = s;
    __syncthreads();
    #pragma unroll
    for (int o = 64; o; o >>= 1) {
        if (tid < o) red[tid] += red[tid + o];
        __syncthreads();
    }
    if (tid == 0) out[blockIdx.x] = red[0];
}

// ---------------- launch ----------------------------------------------------
extern "C" void kernel_launch(void* const* d_in, const int* in_sizes, int n_in,
                              void* d_out, int out_size) {
    const float* x   = (const float*)d_in[0];
    const float* wfc = (const float*)d_in[1];
    if (n_in >= 2 && in_sizes[0] == Cm * NCLS) {  // defensive input-order check
        x   = (const float*)d_in[1];
        wfc = (const float*)d_in[0];
    }
    float* out = (float*)d_out;

    const int smem_hist = WPB * 64 * 32 * (int)sizeof(unsigned int);   // 32 KB
    const int smem_eklm = NB * 57 * (int)sizeof(float);                // ~58 KB
    cudaFuncSetAttribute(k_hist, cudaFuncAttributeMaxDynamicSharedMemorySize, smem_hist);
    cudaFuncSetAttribute(k_eklm, cudaFuncAttributeMaxDynamicSharedMemorySize, smem_eklm);

    // 3 nops: profiled launch (index 3) lands on k_hist this round
    k_nop  <<<1, 32>>>();
    k_nop  <<<1, 32>>>();
    k_nop  <<<1, 32>>>();

    k_hist <<<dim3(25, NCH), WPB * 32, smem_hist>>>(x);
    k_merge<<<dim3(7, 64), 256>>>();
    k_integ<<<64, 256>>>();
    k_eklm <<<1, 256, smem_eklm>>>();
    k_pool <<<(BCm + 7) / 8, 256>>>(x);
    k_fc   <<<Bm * NCLS, 128>>>(wfc, out);
}